// round 4
// baseline (speedup 1.0000x reference)
#include <cuda_runtime.h>
#include <cstdint>

// ---------------------------------------------------------------------------
// Problem constants (shapes fixed by setup_inputs)
// ---------------------------------------------------------------------------
#define N_NODES 50000
#define N_EDGES 400000
#define F_IN    256
#define HID     64
#define N_CLS   32
#define HEADS   8

// ---------------------------------------------------------------------------
// Static scratch (no cudaMalloc allowed)
// ---------------------------------------------------------------------------
__device__ float g_xl1[N_NODES * HEADS * HID];   // 102.4 MB
__device__ float g_xr1[N_NODES * HEADS * HID];   // 102.4 MB
__device__ float g_h1 [N_NODES * HID];           // 12.8 MB
__device__ float g_xl2[N_NODES * HEADS * N_CLS]; // 51.2 MB
__device__ float g_xr2[N_NODES * HEADS * N_CLS]; // 51.2 MB
__device__ int   g_deg   [N_NODES];
__device__ int   g_rowptr[N_NODES + 1];
__device__ int   g_cursor[N_NODES];
__device__ int   g_csr   [N_EDGES + N_NODES];    // edges + self loops
__device__ int   g_is64;                         // edge_index dtype flag

// ---------------------------------------------------------------------------
// edge_index dtype probe.
// If the buffer is int64, every element's high int32 word is 0 (ids < 2^31).
// If int32, odd positions are real src ids (some nonzero).
// We only touch the first nPairs=E logical elements: int32 offsets 0..2E-1,
// which is within bounds for BOTH interpretations (buffer >= 2E int32s).
// ---------------------------------------------------------------------------
__global__ void k_flag_init() { g_is64 = 1; }

__global__ void k_detect(const int* __restrict__ p, int nPairs) {
    int i = blockIdx.x * blockDim.x + threadIdx.x;
    if (i < nPairs && p[2 * i + 1] != 0) g_is64 = 0;   // benign race: only writes 0
}

__device__ __forceinline__ int edge_at(const int* __restrict__ p, int e) {
    if (g_is64) return (int)(((const long long*)p)[e]);
    return p[e];
}

// ---------------------------------------------------------------------------
// CSR build kernels (dst-major, self loops included, range-guarded)
// ---------------------------------------------------------------------------
__global__ void k_init_deg(int* __restrict__ deg, int n) {
    int i = blockIdx.x * blockDim.x + threadIdx.x;
    if (i < n) deg[i] = 1;   // self loop counts as one incoming edge
}

__global__ void k_hist(const int* __restrict__ ei, int E, int* __restrict__ deg) {
    int e = blockIdx.x * blockDim.x + threadIdx.x;
    if (e < E) {
        unsigned d = (unsigned)edge_at(ei, E + e);
        unsigned s = (unsigned)edge_at(ei, e);
        if (d < (unsigned)N_NODES && s < (unsigned)N_NODES)
            atomicAdd(&deg[d], 1);
    }
}

// Single-block exclusive scan (Hillis-Steele over 1024-wide chunks).
__global__ void k_scan(const int* __restrict__ deg, int* __restrict__ rowptr, int n) {
    __shared__ int sm[1024];
    __shared__ int s_carry;
    int t = threadIdx.x;
    if (t == 0) s_carry = 0;
    __syncthreads();
    for (int base = 0; base < n; base += 1024) {
        int i = base + t;
        int v = (i < n) ? deg[i] : 0;
        sm[t] = v;
        __syncthreads();
        #pragma unroll
        for (int off = 1; off < 1024; off <<= 1) {
            int add = (t >= off) ? sm[t - off] : 0;
            __syncthreads();
            sm[t] += add;
            __syncthreads();
        }
        int incl = sm[t];
        int carry = s_carry;
        if (i < n) rowptr[i] = carry + incl - v;   // exclusive
        __syncthreads();
        if (t == 1023) s_carry = carry + incl;
        __syncthreads();
    }
    if (t == 0) rowptr[n] = s_carry;
}

__global__ void k_copy_cursor(const int* __restrict__ rowptr, int* __restrict__ cur, int n) {
    int i = blockIdx.x * blockDim.x + threadIdx.x;
    if (i < n) cur[i] = rowptr[i];
}

__global__ void k_scatter_self(int* __restrict__ cur, int* __restrict__ csr, int n) {
    int i = blockIdx.x * blockDim.x + threadIdx.x;
    if (i < n) csr[atomicAdd(&cur[i], 1)] = i;
}

__global__ void k_scatter_edges(const int* __restrict__ ei, int E,
                                int* __restrict__ cur, int* __restrict__ csr) {
    int e = blockIdx.x * blockDim.x + threadIdx.x;
    if (e < E) {
        unsigned s = (unsigned)edge_at(ei, e);
        unsigned d = (unsigned)edge_at(ei, E + e);
        if (d < (unsigned)N_NODES && s < (unsigned)N_NODES)
            csr[atomicAdd(&cur[d], 1)] = (int)s;
    }
}

// ---------------------------------------------------------------------------
// fp32 SGEMM: C[M,N] = A[M,K] @ B[K,N] (+ bias[n]).
// 128x128x8 block tile, 256 threads, 8x8 microtile.
// Requires K % 8 == 0 and N % 4 == 0 (true: K in {256,64}, N in {512,256,32}).
// ---------------------------------------------------------------------------
__global__ void __launch_bounds__(256)
k_sgemm(const float* __restrict__ A, const float* __restrict__ B,
        float* __restrict__ C, int M, int N, int K,
        const float* __restrict__ bias) {
    constexpr int BM = 128, BN = 128, BK = 8;
    __shared__ float As[BK][BM];
    __shared__ float Bs[BK][BN];

    int tid = threadIdx.x;
    int bm = blockIdx.y * BM;
    int bn = blockIdx.x * BN;
    int tx = tid & 15;       // 0..15 -> N
    int ty = tid >> 4;       // 0..15 -> M

    int aRow = tid >> 1;           // 0..127
    int aCol = (tid & 1) * 4;      // 0 or 4
    int bRow = tid >> 5;           // 0..7
    int bCol = (tid & 31) * 4;     // 0..124

    float acc[8][8];
    #pragma unroll
    for (int i = 0; i < 8; ++i)
        #pragma unroll
        for (int j = 0; j < 8; ++j) acc[i][j] = 0.f;

    for (int k0 = 0; k0 < K; k0 += BK) {
        float4 av = make_float4(0.f, 0.f, 0.f, 0.f);
        if (bm + aRow < M)
            av = *reinterpret_cast<const float4*>(A + (size_t)(bm + aRow) * K + k0 + aCol);
        As[aCol + 0][aRow] = av.x;
        As[aCol + 1][aRow] = av.y;
        As[aCol + 2][aRow] = av.z;
        As[aCol + 3][aRow] = av.w;

        float4 bv = make_float4(0.f, 0.f, 0.f, 0.f);
        if (bn + bCol < N)
            bv = *reinterpret_cast<const float4*>(B + (size_t)(k0 + bRow) * N + bn + bCol);
        *reinterpret_cast<float4*>(&Bs[bRow][bCol]) = bv;

        __syncthreads();
        #pragma unroll
        for (int kk = 0; kk < BK; ++kk) {
            float4 a0 = *reinterpret_cast<const float4*>(&As[kk][ty * 8]);
            float4 a1 = *reinterpret_cast<const float4*>(&As[kk][ty * 8 + 4]);
            float4 b0 = *reinterpret_cast<const float4*>(&Bs[kk][tx * 8]);
            float4 b1 = *reinterpret_cast<const float4*>(&Bs[kk][tx * 8 + 4]);
            float a[8] = {a0.x, a0.y, a0.z, a0.w, a1.x, a1.y, a1.z, a1.w};
            float b[8] = {b0.x, b0.y, b0.z, b0.w, b1.x, b1.y, b1.z, b1.w};
            #pragma unroll
            for (int i = 0; i < 8; ++i)
                #pragma unroll
                for (int j = 0; j < 8; ++j)
                    acc[i][j] = fmaf(a[i], b[j], acc[i][j]);
        }
        __syncthreads();
    }

    #pragma unroll
    for (int i = 0; i < 8; ++i) {
        int row = bm + ty * 8 + i;
        if (row >= M) continue;
        #pragma unroll
        for (int j = 0; j < 8; ++j) {
            int col = bn + tx * 8 + j;
            if (col < N) {
                float v = acc[i][j];
                if (bias) v += bias[col];
                C[(size_t)row * N + col] = v;
            }
        }
    }
}

// ---------------------------------------------------------------------------
// GATv2 edge+softmax+aggregate, fused per dst node.
// One block per dst node, 8 warps = 8 heads, lane = channel (C/32 chans/lane).
// alpha = exp(logit)/denom done as unnormalized sum then divide (no max-shift;
// logits are O(1) so fp32 exp is safe; ratio is mathematically identical).
// ---------------------------------------------------------------------------
template <int C, bool RELU, bool ADD_RES>
__global__ void __launch_bounds__(256)
k_gatv2(const float* __restrict__ xl, const float* __restrict__ xr,
        const float* __restrict__ att, const float* __restrict__ bias,
        const int* __restrict__ rowptr, const int* __restrict__ csr,
        const float* __restrict__ resid, float* __restrict__ out) {
    constexpr int H = HEADS;
    constexpr int KC = C / 32;       // channels per lane (2 for C=64, 1 for C=32)
    int node = blockIdx.x;
    int w = threadIdx.x >> 5;        // head
    int l = threadIdx.x & 31;        // lane

    const float* xr_row = xr + (size_t)node * H * C + w * C;
    float xrv[KC], attv[KC], accv[KC];
    #pragma unroll
    for (int k = 0; k < KC; ++k) {
        xrv[k]  = xr_row[l + 32 * k];
        attv[k] = att[w * C + l + 32 * k];
        accv[k] = 0.f;
    }
    float denom = 0.f;

    int beg = rowptr[node], end = rowptr[node + 1];
    for (int idx = beg; idx < end; ++idx) {
        int s = csr[idx];
        const float* xl_row = xl + (size_t)s * H * C + w * C;
        float xlv[KC];
        float partial = 0.f;
        #pragma unroll
        for (int k = 0; k < KC; ++k) {
            xlv[k] = xl_row[l + 32 * k];
            float v = xlv[k] + xrv[k];
            v = (v > 0.f) ? v : 0.2f * v;      // leaky_relu(0.2)
            partial = fmaf(attv[k], v, partial);
        }
        #pragma unroll
        for (int off = 16; off > 0; off >>= 1)
            partial += __shfl_xor_sync(0xffffffffu, partial, off);
        float p = __expf(partial);
        denom += p;
        #pragma unroll
        for (int k = 0; k < KC; ++k)
            accv[k] = fmaf(p, xlv[k], accv[k]);
    }

    // head mean via smem
    __shared__ float sh[H * C];
    float inv = 1.f / denom;
    #pragma unroll
    for (int k = 0; k < KC; ++k)
        sh[w * C + l + 32 * k] = accv[k] * inv;
    __syncthreads();

    if (threadIdx.x < C) {
        int c = threadIdx.x;
        float s = 0.f;
        #pragma unroll
        for (int h = 0; h < H; ++h) s += sh[h * C + c];
        s = s * (1.f / H) + bias[c];
        if (RELU) s = fmaxf(s, 0.f);
        if (ADD_RES) s += resid[(size_t)node * C + c];
        out[(size_t)node * C + c] = s;
    }
}

// ---------------------------------------------------------------------------
// Launch
// ---------------------------------------------------------------------------
static inline int cdiv(int a, int b) { return (a + b - 1) / b; }

extern "C" void kernel_launch(void* const* d_in, const int* in_sizes, int n_in,
                              void* d_out, int out_size) {
    const float* x    = (const float*)d_in[0];
    const int*   ei   = (const int*)d_in[1];     // int32 or int64, detected on device
    const float* Wl1  = (const float*)d_in[2];
    const float* Wr1  = (const float*)d_in[3];
    const float* att1 = (const float*)d_in[4];
    const float* b1   = (const float*)d_in[5];
    const float* Wl2  = (const float*)d_in[6];
    const float* Wr2  = (const float*)d_in[7];
    const float* att2 = (const float*)d_in[8];
    const float* b2   = (const float*)d_in[9];
    const float* Wlin = (const float*)d_in[10];
    const float* blin = (const float*)d_in[11];
    float* out = (float*)d_out;

    const int N = in_sizes[0] / F_IN;   // 50000
    const int E = in_sizes[1] / 2;      // 400000 (element count, dtype-independent)

    float *xl1, *xr1, *xl2, *xr2, *h1;
    int *deg, *rowptr, *cursor, *csr;
    cudaGetSymbolAddress((void**)&xl1,    g_xl1);
    cudaGetSymbolAddress((void**)&xr1,    g_xr1);
    cudaGetSymbolAddress((void**)&h1,     g_h1);
    cudaGetSymbolAddress((void**)&xl2,    g_xl2);
    cudaGetSymbolAddress((void**)&xr2,    g_xr2);
    cudaGetSymbolAddress((void**)&deg,    g_deg);
    cudaGetSymbolAddress((void**)&rowptr, g_rowptr);
    cudaGetSymbolAddress((void**)&cursor, g_cursor);
    cudaGetSymbolAddress((void**)&csr,    g_csr);

    // ---- edge_index dtype detection (all device-side, deterministic) ----
    k_flag_init<<<1, 1>>>();
    k_detect<<<cdiv(E, 256), 256>>>(ei, E);

    // ---- CSR build (by dst, self loops included) ----
    k_init_deg<<<cdiv(N, 256), 256>>>(deg, N);
    k_hist<<<cdiv(E, 256), 256>>>(ei, E, deg);
    k_scan<<<1, 1024>>>(deg, rowptr, N);
    k_copy_cursor<<<cdiv(N, 256), 256>>>(rowptr, cursor, N);
    k_scatter_self<<<cdiv(N, 256), 256>>>(cursor, csr, N);
    k_scatter_edges<<<cdiv(E, 256), 256>>>(ei, E, cursor, csr);

    // ---- Layer-1 transforms + residual ----
    {
        dim3 g(cdiv(HEADS * HID, 128), cdiv(N, 128));      // N=512
        k_sgemm<<<g, 256>>>(x, Wl1, xl1, N, HEADS * HID, F_IN, nullptr);
        k_sgemm<<<g, 256>>>(x, Wr1, xr1, N, HEADS * HID, F_IN, nullptr);
    }
    {
        dim3 g(cdiv(N_CLS, 128), cdiv(N, 128));            // N=32 -> residual into d_out
        k_sgemm<<<g, 256>>>(x, Wlin, out, N, N_CLS, F_IN, blin);
    }

    // ---- GAT layer 1 (relu) -> h1 ----
    k_gatv2<HID, true, false><<<N, 256>>>(xl1, xr1, att1, b1, rowptr, csr, nullptr, h1);

    // ---- Layer-2 transforms ----
    {
        dim3 g(cdiv(HEADS * N_CLS, 128), cdiv(N, 128));    // N=256
        k_sgemm<<<g, 256>>>(h1, Wl2, xl2, N, HEADS * N_CLS, HID, nullptr);
        k_sgemm<<<g, 256>>>(h1, Wr2, xr2, N, HEADS * N_CLS, HID, nullptr);
    }

    // ---- GAT layer 2 + residual -> d_out ----
    k_gatv2<N_CLS, false, true><<<N, 256>>>(xl2, xr2, att2, b2, rowptr, csr, out, out);
}